// round 1
// baseline (speedup 1.0000x reference)
#include <cuda_runtime.h>

// Problem constants
#define B  4096
#define E  512
#define T  32
#define H  256
#define IT 5
#define EPS 1e-6f

#define BT  32    // batch rows per block
#define ECH 64    // e-chunk staged in smem

// ---------------- packed f32x2 helpers (sm_100+ PTX) ----------------
__device__ __forceinline__ unsigned long long pack2(float lo, float hi) {
    unsigned long long r;
    asm("mov.b64 %0, {%1, %2};" : "=l"(r) : "f"(lo), "f"(hi));
    return r;
}
__device__ __forceinline__ void fma2(unsigned long long& d,
                                     unsigned long long a,
                                     unsigned long long b) {
    asm("fma.rn.f32x2 %0, %1, %2, %0;" : "+l"(d) : "l"(a), "l"(b));
}
__device__ __forceinline__ float2 unpack2(unsigned long long v) {
    float lo, hi;
    asm("mov.b64 {%0, %1}, %2;" : "=f"(lo), "=f"(hi) : "l"(v));
    return make_float2(lo, hi);
}

__global__ __launch_bounds__(256, 2)
void sparse_block_kernel(const float* __restrict__ x,
                         const float* __restrict__ w_in,
                         const float* __restrict__ w_val,
                         const float* __restrict__ alphas,
                         const float* __restrict__ scales,
                         const float* __restrict__ gamma,
                         const float* __restrict__ beta,
                         float* __restrict__ out)
{
    __shared__ float xs[BT * ECH];     // [row][e]   8 KB
    __shared__ float red[8][16];       // [warp][row / row+8]  512 B

    const int tid  = threadIdx.x;
    const int tcol = tid & 63;         // h-group: h0 = tcol*4
    const int trow = tid >> 6;         // row-group: rows trow*8 .. +7
    const int h0   = tcol * 4;
    const int b0   = blockIdx.x * BT;
    const int t    = blockIdx.y;

    const float* wi_base = w_in  + (size_t)t * E * H + h0;
    const float* wv_base = w_val + (size_t)t * E * H + h0;

    // ---------------- dual GEMM: hidden & value ----------------
    unsigned long long acch[8][2], accv[8][2];
    #pragma unroll
    for (int r = 0; r < 8; r++) {
        acch[r][0] = 0ull; acch[r][1] = 0ull;
        accv[r][0] = 0ull; accv[r][1] = 0ull;
    }

    for (int ec = 0; ec < E; ec += ECH) {
        // cooperative stage of x[b0..b0+31][ec..ec+63]
        {
            int idx = tid * 8;
            int row = idx >> 6;       // / ECH
            int col = idx & 63;
            const float4* src =
                reinterpret_cast<const float4*>(x + (size_t)(b0 + row) * E + ec + col);
            float4 v0 = src[0];
            float4 v1 = src[1];
            float4* dst = reinterpret_cast<float4*>(&xs[row * ECH + col]);
            dst[0] = v0; dst[1] = v1;
        }
        __syncthreads();

        #pragma unroll 8
        for (int e = 0; e < ECH; e++) {
            const ulonglong2 wi =
                *reinterpret_cast<const ulonglong2*>(wi_base + (size_t)(ec + e) * H);
            const ulonglong2 wv =
                *reinterpret_cast<const ulonglong2*>(wv_base + (size_t)(ec + e) * H);
            #pragma unroll
            for (int r = 0; r < 8; r++) {
                float xv = xs[(trow * 8 + r) * ECH + e];   // warp-uniform -> broadcast
                unsigned long long xx = pack2(xv, xv);
                fma2(acch[r][0], xx, wi.x);
                fma2(acch[r][1], xx, wi.y);
                fma2(accv[r][0], xx, wv.x);
                fma2(accv[r][1], xx, wv.y);
            }
        }
        __syncthreads();
    }

    // ---------------- unpack: x_t = relu(hidden), vv = value ----------------
    float xt[8][4], vv[8][4];
    #pragma unroll
    for (int r = 0; r < 8; r++) {
        float2 a0 = unpack2(acch[r][0]);
        float2 a1 = unpack2(acch[r][1]);
        xt[r][0] = fmaxf(a0.x, 0.0f);
        xt[r][1] = fmaxf(a0.y, 0.0f);
        xt[r][2] = fmaxf(a1.x, 0.0f);
        xt[r][3] = fmaxf(a1.y, 0.0f);
        float2 v0 = unpack2(accv[r][0]);
        float2 v1 = unpack2(accv[r][1]);
        vv[r][0] = v0.x; vv[r][1] = v0.y; vv[r][2] = v1.x; vv[r][3] = v1.y;
    }

    const int wid  = tid >> 5;      // 0..7 ; warps (2*trow, 2*trow+1) cover same rows
    const int lane = tid & 31;
    const float inv_h = 1.0f / (float)H;

    // ---------------- iterative competitive inhibition ----------------
    #pragma unroll
    for (int it = 0; it < IT; it++) {
        const float a = alphas[t * IT + it];
        float psum[8];
        #pragma unroll
        for (int r = 0; r < 8; r++)
            psum[r] = (xt[r][0] + xt[r][1]) + (xt[r][2] + xt[r][3]);
        #pragma unroll
        for (int off = 16; off > 0; off >>= 1) {
            #pragma unroll
            for (int r = 0; r < 8; r++)
                psum[r] += __shfl_xor_sync(0xffffffffu, psum[r], off);
        }
        if (lane == 0) {
            #pragma unroll
            for (int r = 0; r < 8; r++) red[wid][r] = psum[r];
        }
        __syncthreads();
        #pragma unroll
        for (int r = 0; r < 8; r++) {
            float m = (red[trow * 2][r] + red[trow * 2 + 1][r]) * inv_h;
            float d = a * m;
            #pragma unroll
            for (int c = 0; c < 4; c++)
                xt[r][c] = fmaxf(xt[r][c] - d, 0.0f);
        }
        __syncthreads();
    }

    // ---------------- gated value + LayerNorm ----------------
    const float4 sc = *reinterpret_cast<const float4*>(scales + (size_t)t * H + h0);
    const float4 gm = *reinterpret_cast<const float4*>(gamma  + (size_t)t * H + h0);
    const float4 bt = *reinterpret_cast<const float4*>(beta   + (size_t)t * H + h0);

    float s[8][4];
    #pragma unroll
    for (int r = 0; r < 8; r++) {
        s[r][0] = sc.x * xt[r][0] * vv[r][0];
        s[r][1] = sc.y * xt[r][1] * vv[r][1];
        s[r][2] = sc.z * xt[r][2] * vv[r][2];
        s[r][3] = sc.w * xt[r][3] * vv[r][3];
    }

    // combined sum & sum-of-squares reduction
    float psum[8], psq[8];
    #pragma unroll
    for (int r = 0; r < 8; r++) {
        psum[r] = (s[r][0] + s[r][1]) + (s[r][2] + s[r][3]);
        psq[r]  = (s[r][0]*s[r][0] + s[r][1]*s[r][1])
                + (s[r][2]*s[r][2] + s[r][3]*s[r][3]);
    }
    #pragma unroll
    for (int off = 16; off > 0; off >>= 1) {
        #pragma unroll
        for (int r = 0; r < 8; r++) {
            psum[r] += __shfl_xor_sync(0xffffffffu, psum[r], off);
            psq[r]  += __shfl_xor_sync(0xffffffffu, psq[r],  off);
        }
    }
    if (lane == 0) {
        #pragma unroll
        for (int r = 0; r < 8; r++) {
            red[wid][r]     = psum[r];
            red[wid][8 + r] = psq[r];
        }
    }
    __syncthreads();

    #pragma unroll
    for (int r = 0; r < 8; r++) {
        float sum = red[trow * 2][r]     + red[trow * 2 + 1][r];
        float sq  = red[trow * 2][8 + r] + red[trow * 2 + 1][8 + r];
        float mu  = sum * inv_h;
        float var = fmaxf(sq * inv_h - mu * mu, 0.0f);
        float inv = rsqrtf(var + EPS);
        float4 o;
        o.x = (s[r][0] - mu) * inv * gm.x + bt.x;
        o.y = (s[r][1] - mu) * inv * gm.y + bt.y;
        o.z = (s[r][2] - mu) * inv * gm.z + bt.z;
        o.w = (s[r][3] - mu) * inv * gm.w + bt.w;
        int b = b0 + trow * 8 + r;
        *reinterpret_cast<float4*>(out + ((size_t)b * T + t) * H + h0) = o;
    }
}

extern "C" void kernel_launch(void* const* d_in, const int* in_sizes, int n_in,
                              void* d_out, int out_size) {
    const float* x      = (const float*)d_in[0];
    const float* w_in   = (const float*)d_in[1];
    const float* w_val  = (const float*)d_in[2];
    const float* alphas = (const float*)d_in[3];
    const float* scales = (const float*)d_in[4];
    const float* gamma  = (const float*)d_in[5];
    const float* beta   = (const float*)d_in[6];
    float* out = (float*)d_out;

    dim3 grid(B / BT, T);
    sparse_block_kernel<<<grid, 256>>>(x, w_in, w_val, alphas, scales,
                                       gamma, beta, out);
}

// round 3
// speedup vs baseline: 3.8179x; 3.8179x over previous
#include <cuda_runtime.h>
#include <cuda_fp16.h>
#include <cstdint>

// ---------------- problem constants ----------------
constexpr int Bq = 4096;
constexpr int Eq = 512;   // K
constexpr int Tq = 32;
constexpr int Hq = 256;
constexpr int ITq = 5;
constexpr int NN = 512;   // hidden(256) || value(256)
#define EPSq 1e-6f

// ---------------- GEMM tiling ----------------
constexpr int MT  = 64;          // CTA rows (batch)
constexpr int KC  = 32;          // k elements per stage
constexpr int NCH = Eq / KC;     // 16 stages of K
constexpr int PIT = 40;          // halves per smem row (32 + 8 pad) = 80 B
constexpr int A_HALF  = MT * PIT;             // halves, one of {hi,lo}
constexpr int STAGE_A = 2 * A_HALF;           // hi+lo
constexpr int STAGE_B = NN * PIT;
constexpr int STAGE   = STAGE_A + STAGE_B;    // halves (25600 = 51200 B)
constexpr int NSTG    = 3;
constexpr int EPI_PIT = NN + 8;               // floats, epilogue pitch
constexpr int SMEM_BYTES =
    (NSTG * STAGE * 2 > MT * EPI_PIT * 4) ? NSTG * STAGE * 2 : MT * EPI_PIT * 4;

// ---------------- device scratch ----------------
__device__ __half g_xhi[(size_t)Bq * Eq];                 // 4 MB
__device__ __half g_xlo[(size_t)Bq * Eq];                 // 4 MB
__device__ __half g_wT [(size_t)Tq * NN * Eq];            // 16 MB  [t][n][e]

// ---------------- asm helpers (all sm_80-class, compute_103-safe) ----------
__device__ __forceinline__ uint32_t smem_u32(const void* p) {
    uint32_t a;
    asm("{ .reg .u64 t; cvta.to.shared.u64 t, %1; cvt.u32.u64 %0, t; }"
        : "=r"(a) : "l"(p));
    return a;
}
#define CP16(dst, src) \
    asm volatile("cp.async.cg.shared.global [%0], [%1], 16;" \
                 :: "r"(dst), "l"(src) : "memory")
#define CP_COMMIT() asm volatile("cp.async.commit_group;" ::: "memory")
#define CP_WAIT(n)  asm volatile("cp.async.wait_group %0;" :: "n"(n) : "memory")

__device__ __forceinline__ void ldm4(uint32_t* r, uint32_t addr) {
    asm volatile("ldmatrix.sync.aligned.m8n8.x4.shared.b16 {%0,%1,%2,%3}, [%4];"
        : "=r"(r[0]), "=r"(r[1]), "=r"(r[2]), "=r"(r[3]) : "r"(addr));
}
__device__ __forceinline__ void mma16816(float* d, const uint32_t* a,
                                         const uint32_t* b) {
    asm volatile(
        "mma.sync.aligned.m16n8k16.row.col.f32.f16.f16.f32 "
        "{%0,%1,%2,%3},{%4,%5,%6,%7},{%8,%9},{%0,%1,%2,%3};"
        : "+f"(d[0]), "+f"(d[1]), "+f"(d[2]), "+f"(d[3])
        : "r"(a[0]), "r"(a[1]), "r"(a[2]), "r"(a[3]), "r"(b[0]), "r"(b[1]));
}

// ---------------- kernel 1: split x into fp16 hi/lo ----------------
__global__ __launch_bounds__(256)
void convert_x_kernel(const float* __restrict__ x) {
    const size_t i0 = ((size_t)blockIdx.x * 256 + threadIdx.x) * 8;
    __half hi[8], lo[8];
    #pragma unroll
    for (int j = 0; j < 8; j++) {
        float v = x[i0 + j];
        __half h = __float2half_rn(v);
        hi[j] = h;
        lo[j] = __float2half_rn(v - __half2float(h));
    }
    *reinterpret_cast<uint4*>(&g_xhi[i0]) = *reinterpret_cast<uint4*>(hi);
    *reinterpret_cast<uint4*>(&g_xlo[i0]) = *reinterpret_cast<uint4*>(lo);
}

// ---------------- kernel 2: transpose+convert w -> wT[t][n][e] fp16 --------
__global__ __launch_bounds__(256)
void convert_w_kernel(const float* __restrict__ w_in,
                      const float* __restrict__ w_val) {
    __shared__ float tile[32][33];
    const int e0 = blockIdx.x * 32;
    const int h0 = blockIdx.y * 32;
    const int z  = blockIdx.z;           // 0..63
    const int m  = z >> 5;               // 0: w_in, 1: w_val
    const int t  = z & 31;
    const float* src = (m ? w_val : w_in) + (size_t)t * Eq * Hq;
    const int tx = threadIdx.x & 31;
    const int ty = threadIdx.x >> 5;
    #pragma unroll
    for (int r = ty; r < 32; r += 8)
        tile[r][tx] = src[(size_t)(e0 + r) * Hq + h0 + tx];
    __syncthreads();
    __half* dst = g_wT + ((size_t)t * NN + (size_t)m * Hq) * Eq;
    #pragma unroll
    for (int r = ty; r < 32; r += 8)
        dst[(size_t)(h0 + r) * Eq + e0 + tx] = __float2half_rn(tile[tx][r]);
}

// ---------------- kernel 3: fused GEMM (mma.sync fp16-split) + epilogue ----
__global__ __launch_bounds__(512, 1)
void gemm_fused_kernel(const float* __restrict__ alphas,
                       const float* __restrict__ scales,
                       const float* __restrict__ gamma,
                       const float* __restrict__ beta,
                       float* __restrict__ out)
{
    extern __shared__ __half smh[];
    const uint32_t sb = smem_u32(smh);

    const int tid  = threadIdx.x;
    const int wid  = tid >> 5;
    const int lane = tid & 31;
    const int m0   = (wid >> 3) * 32;   // warp m origin (0/32)
    const int n0w  = (wid & 7) * 64;    // warp n origin (0..448)

    const int b0  = blockIdx.x * MT;
    const int tok = blockIdx.y;

    const __half* Ahi = g_xhi + (size_t)b0 * Eq;
    const __half* Alo = g_xlo + (size_t)b0 * Eq;
    const __half* Bw  = g_wT + (size_t)tok * NN * Eq;

    float acc[2][8][4];
    #pragma unroll
    for (int i = 0; i < 2; i++)
        #pragma unroll
        for (int j = 0; j < 8; j++)
            #pragma unroll
            for (int k = 0; k < 4; k++) acc[i][j][k] = 0.0f;

    // ---- stage issue: A (hi+lo, 512 ops) + B (2048 ops), 5 ops/thread ----
    auto issue_stage = [&](int c) {
        const int s = c % NSTG;
        const uint32_t base = sb + (uint32_t)(s * STAGE) * 2;
        {
            const int half = tid >> 8;          // 0: hi, 1: lo
            const int pos  = tid & 255;
            const int row  = pos >> 2;
            const int ch   = pos & 3;
            const __half* src = (half ? Alo : Ahi) + (size_t)row * Eq + c * KC + ch * 8;
            CP16(base + (uint32_t)(half * A_HALF + row * PIT) * 2 + ch * 16, src);
        }
        const uint32_t bbase = base + (uint32_t)STAGE_A * 2;
        #pragma unroll
        for (int j = 0; j < 4; j++) {
            const int pos = tid + j * 512;
            const int row = pos >> 2;
            const int ch  = pos & 3;
            const __half* src = Bw + (size_t)row * Eq + c * KC + ch * 8;
            CP16(bbase + (uint32_t)(row * PIT) * 2 + ch * 16, src);
        }
    };

    issue_stage(0); CP_COMMIT();
    issue_stage(1); CP_COMMIT();

    // ---- main K loop ----
    for (int c = 0; c < NCH; c++) {
        if (c + 1 == NCH) { CP_WAIT(0); } else { CP_WAIT(1); }
        __syncthreads();
        if (c + 2 < NCH) { issue_stage(c + 2); CP_COMMIT(); }

        const int s = c % NSTG;
        const uint32_t abase = sb + (uint32_t)(s * STAGE) * 2;
        const uint32_t lbase = abase + (uint32_t)A_HALF * 2;
        const uint32_t bbase = abase + (uint32_t)STAGE_A * 2;

        #pragma unroll
        for (int ks = 0; ks < 2; ks++) {
            const uint32_t koff = ks * 32 + ((lane >> 4) << 4);  // bytes
            uint32_t ah[2][4], al[2][4], bb[4][4];
            #pragma unroll
            for (int mf = 0; mf < 2; mf++) {
                const uint32_t r = m0 + mf * 16 + (lane & 15);
                ldm4(ah[mf], abase + r * 80 + koff);
                ldm4(al[mf], lbase + r * 80 + koff);
            }
            #pragma unroll
            for (int nb = 0; nb < 4; nb++) {
                const uint32_t r = n0w + nb * 16 + (lane & 7) + ((lane >> 4) << 3);
                const uint32_t kh = (lane >> 3) & 1;
                ldm4(bb[nb], bbase + r * 80 + ks * 32 + kh * 16);
            }
            #pragma unroll
            for (int mf = 0; mf < 2; mf++)
                #pragma unroll
                for (int nf = 0; nf < 8; nf++) {
                    const uint32_t* bp = &bb[nf >> 1][(nf & 1) * 2];
                    mma16816(acc[mf][nf], ah[mf], bp);
                    mma16816(acc[mf][nf], al[mf], bp);
                }
        }
        __syncthreads();
    }

    // ---- epilogue: accums -> smem [m][n] ----
    float* es = reinterpret_cast<float*>(smh);
    #pragma unroll
    for (int mf = 0; mf < 2; mf++)
        #pragma unroll
        for (int nf = 0; nf < 8; nf++) {
            const int row = m0 + mf * 16 + (lane >> 2);
            const int col = n0w + nf * 8 + 2 * (lane & 3);
            es[row * EPI_PIT + col]           = acc[mf][nf][0];
            es[row * EPI_PIT + col + 1]       = acc[mf][nf][1];
            es[(row + 8) * EPI_PIT + col]     = acc[mf][nf][2];
            es[(row + 8) * EPI_PIT + col + 1] = acc[mf][nf][3];
        }
    __syncthreads();

    // ---- per-row inhibition + LayerNorm; warp w -> rows 4w..4w+3 ----
    float sc[8], gm[8], bt[8], av[ITq];
    #pragma unroll
    for (int j = 0; j < 8; j++) {
        sc[j] = scales[tok * Hq + 32 * j + lane];
        gm[j] = gamma [tok * Hq + 32 * j + lane];
        bt[j] = beta  [tok * Hq + 32 * j + lane];
    }
    #pragma unroll
    for (int i = 0; i < ITq; i++) av[i] = alphas[tok * ITq + i];

    constexpr float INVH = 1.0f / (float)Hq;
    #pragma unroll
    for (int rr = 0; rr < 4; rr++) {
        const int lrow = wid * 4 + rr;
        float xt[8], xv[8];
        #pragma unroll
        for (int j = 0; j < 8; j++) {
            xt[j] = fmaxf(es[lrow * EPI_PIT + 32 * j + lane], 0.0f);
            xv[j] = es[lrow * EPI_PIT + 256 + 32 * j + lane];
        }
        #pragma unroll
        for (int it = 0; it < ITq; it++) {
            float s = 0.0f;
            #pragma unroll
            for (int j = 0; j < 8; j++) s += xt[j];
            #pragma unroll
            for (int off = 16; off > 0; off >>= 1)
                s += __shfl_xor_sync(0xffffffffu, s, off);
            const float d = av[it] * s * INVH;
            #pragma unroll
            for (int j = 0; j < 8; j++) xt[j] = fmaxf(xt[j] - d, 0.0f);
        }
        float sv[8], sum = 0.0f, sq = 0.0f;
        #pragma unroll
        for (int j = 0; j < 8; j++) {
            sv[j] = sc[j] * xt[j] * xv[j];
            sum += sv[j];
            sq  += sv[j] * sv[j];
        }
        #pragma unroll
        for (int off = 16; off > 0; off >>= 1) {
            sum += __shfl_xor_sync(0xffffffffu, sum, off);
            sq  += __shfl_xor_sync(0xffffffffu, sq,  off);
        }
        const float mu  = sum * INVH;
        const float var = fmaxf(sq * INVH - mu * mu, 0.0f);
        const float inv = rsqrtf(var + EPSq);
        const int b = b0 + lrow;
        float* op = out + ((size_t)b * Tq + tok) * Hq;
        #pragma unroll
        for (int j = 0; j < 8; j++)
            op[32 * j + lane] = (sv[j] - mu) * inv * gm[j] + bt[j];
    }
}

// ---------------- host launch ----------------
extern "C" void kernel_launch(void* const* d_in, const int* in_sizes, int n_in,
                              void* d_out, int out_size) {
    const float* x      = (const float*)d_in[0];
    const float* w_in   = (const float*)d_in[1];
    const float* w_val  = (const float*)d_in[2];
    const float* alphas = (const float*)d_in[3];
    const float* scales = (const float*)d_in[4];
    const float* gamma  = (const float*)d_in[5];
    const float* beta   = (const float*)d_in[6];
    float* out = (float*)d_out;

    convert_x_kernel<<<(Bq * Eq) / (256 * 8), 256>>>(x);

    dim3 wgrid(Eq / 32, Hq / 32, 2 * Tq);
    convert_w_kernel<<<wgrid, 256>>>(w_in, w_val);

    cudaFuncSetAttribute(gemm_fused_kernel,
                         cudaFuncAttributeMaxDynamicSharedMemorySize, SMEM_BYTES);
    dim3 grid(Bq / MT, Tq);
    gemm_fused_kernel<<<grid, 512, SMEM_BYTES>>>(alphas, scales, gamma, beta, out);
}

// round 4
// speedup vs baseline: 5.3227x; 1.3941x over previous
#include <cuda_runtime.h>
#include <cuda_fp16.h>
#include <cstdint>

// ---------------- problem constants ----------------
constexpr int Bq = 4096;
constexpr int Eq = 512;   // K
constexpr int Tq = 32;
constexpr int Hq = 256;
constexpr int ITq = 5;
constexpr int NN = 512;   // hidden(256) || value(256)
#define EPSq 1e-6f

// ---------------- GEMM tiling ----------------
constexpr int MT  = 64;          // CTA rows (batch)
constexpr int KC  = 32;          // k elements per stage
constexpr int NCH = Eq / KC;     // 16 stages of K
constexpr int PIT = 40;          // halves per smem row (32 + 8 pad) = 80 B
constexpr int A_HALVES = MT * PIT;            // 2560 halves
constexpr int STAGE    = A_HALVES + NN * PIT; // 23040 halves = 46080 B
constexpr int NSTG     = 4;
constexpr int EPI_PIT  = NN + 8;              // floats
constexpr int SMEM_BYTES =
    (NSTG * STAGE * 2 > MT * EPI_PIT * 4) ? NSTG * STAGE * 2 : MT * EPI_PIT * 4;

// ---------------- device scratch ----------------
__device__ __half g_xh[(size_t)Bq * Eq];                  // 4 MB
__device__ __half g_wT[(size_t)Tq * NN * Eq];             // 16 MB  [t][n][e]

// ---------------- asm helpers (sm_80-class, compute_103-safe) ----------
__device__ __forceinline__ uint32_t smem_u32(const void* p) {
    uint32_t a;
    asm("{ .reg .u64 t; cvta.to.shared.u64 t, %1; cvt.u32.u64 %0, t; }"
        : "=r"(a) : "l"(p));
    return a;
}
#define CP16(dst, src) \
    asm volatile("cp.async.cg.shared.global [%0], [%1], 16;" \
                 :: "r"(dst), "l"(src) : "memory")
#define CP_COMMIT() asm volatile("cp.async.commit_group;" ::: "memory")
#define CP_WAIT(n)  asm volatile("cp.async.wait_group %0;" :: "n"(n) : "memory")

__device__ __forceinline__ void ldm4(uint32_t* r, uint32_t addr) {
    asm volatile("ldmatrix.sync.aligned.m8n8.x4.shared.b16 {%0,%1,%2,%3}, [%4];"
        : "=r"(r[0]), "=r"(r[1]), "=r"(r[2]), "=r"(r[3]) : "r"(addr));
}
__device__ __forceinline__ void mma16816(float* d, const uint32_t* a,
                                         const uint32_t* b) {
    asm volatile(
        "mma.sync.aligned.m16n8k16.row.col.f32.f16.f16.f32 "
        "{%0,%1,%2,%3},{%4,%5,%6,%7},{%8,%9},{%0,%1,%2,%3};"
        : "+f"(d[0]), "+f"(d[1]), "+f"(d[2]), "+f"(d[3])
        : "r"(a[0]), "r"(a[1]), "r"(a[2]), "r"(a[3]), "r"(b[0]), "r"(b[1]));
}

// ---------------- kernel 1: fused conversions ----------------
// blocks [0, 1024):      x fp32 -> fp16
// blocks [1024, 9216):   w transpose+convert -> wT[t][n][e] fp16
__global__ __launch_bounds__(256)
void convert_kernel(const float* __restrict__ x,
                    const float* __restrict__ w_in,
                    const float* __restrict__ w_val) {
    __shared__ float tile[32][33];
    if (blockIdx.x < 1024) {
        const size_t i0 = ((size_t)blockIdx.x * 256 + threadIdx.x) * 8;
        __half h[8];
        #pragma unroll
        for (int j = 0; j < 8; j++) h[j] = __float2half_rn(x[i0 + j]);
        *reinterpret_cast<uint4*>(&g_xh[i0]) = *reinterpret_cast<uint4*>(h);
        return;
    }
    const int bz = blockIdx.x - 1024;       // 0..8191
    const int e0 = (bz & 15) * 32;
    const int h0 = ((bz >> 4) & 7) * 32;
    const int z  = bz >> 7;                 // 0..63
    const int m  = z >> 5;                  // 0: w_in, 1: w_val
    const int t  = z & 31;
    const float* src = (m ? w_val : w_in) + (size_t)t * Eq * Hq;
    const int tx = threadIdx.x & 31;
    const int ty = threadIdx.x >> 5;
    #pragma unroll
    for (int r = ty; r < 32; r += 8)
        tile[r][tx] = src[(size_t)(e0 + r) * Hq + h0 + tx];
    __syncthreads();
    __half* dst = g_wT + ((size_t)t * NN + (size_t)m * Hq) * Eq;
    #pragma unroll
    for (int r = ty; r < 32; r += 8)
        dst[(size_t)(h0 + r) * Eq + e0 + tx] = __float2half_rn(tile[tx][r]);
}

// ---------------- kernel 2: fused GEMM (single-pass fp16) + epilogue ----
__global__ __launch_bounds__(512, 1)
void gemm_fused_kernel(const float* __restrict__ alphas,
                       const float* __restrict__ scales,
                       const float* __restrict__ gamma,
                       const float* __restrict__ beta,
                       float* __restrict__ out)
{
    extern __shared__ __half smh[];
    const uint32_t sb = smem_u32(smh);

    const int tid  = threadIdx.x;
    const int wid  = tid >> 5;
    const int lane = tid & 31;
    const int m0   = (wid >> 3) * 32;   // warp m origin (0/32)
    const int n0w  = (wid & 7) * 64;    // warp n origin (0..448)

    const int b0  = blockIdx.x * MT;
    const int tok = blockIdx.y;

    const __half* Ah = g_xh + (size_t)b0 * Eq;
    const __half* Bw = g_wT + (size_t)tok * NN * Eq;

    float acc[2][8][4];
    #pragma unroll
    for (int i = 0; i < 2; i++)
        #pragma unroll
        for (int j = 0; j < 8; j++)
            #pragma unroll
            for (int k = 0; k < 4; k++) acc[i][j][k] = 0.0f;

    // ---- stage issue: A (256 ops) + B (2048 ops) ----
    auto issue_stage = [&](int c) {
        const int s = c & (NSTG - 1);
        const uint32_t base = sb + (uint32_t)(s * STAGE) * 2;
        if (tid < 256) {
            const int row = tid >> 2;
            const int ch  = tid & 3;
            const __half* src = Ah + (size_t)row * Eq + c * KC + ch * 8;
            CP16(base + (uint32_t)(row * PIT) * 2 + ch * 16, src);
        }
        const uint32_t bbase = base + (uint32_t)A_HALVES * 2;
        #pragma unroll
        for (int j = 0; j < 4; j++) {
            const int pos = tid + j * 512;
            const int row = pos >> 2;
            const int ch  = pos & 3;
            const __half* src = Bw + (size_t)row * Eq + c * KC + ch * 8;
            CP16(bbase + (uint32_t)(row * PIT) * 2 + ch * 16, src);
        }
    };

    issue_stage(0); CP_COMMIT();
    issue_stage(1); CP_COMMIT();
    issue_stage(2); CP_COMMIT();

    // ---- main K loop: one sync per chunk ----
    for (int c = 0; c < NCH; c++) {
        if (c < NCH - 2)       { CP_WAIT(2); }
        else if (c == NCH - 2) { CP_WAIT(1); }
        else                   { CP_WAIT(0); }
        __syncthreads();
        if (c + 3 < NCH) { issue_stage(c + 3); CP_COMMIT(); }

        const int s = c & (NSTG - 1);
        const uint32_t abase = sb + (uint32_t)(s * STAGE) * 2;
        const uint32_t bbase = abase + (uint32_t)A_HALVES * 2;

        #pragma unroll
        for (int ks = 0; ks < 2; ks++) {
            const uint32_t koff = ks * 32 + ((lane >> 4) << 4);  // bytes
            uint32_t ah[2][4], bb[4][4];
            #pragma unroll
            for (int mf = 0; mf < 2; mf++) {
                const uint32_t r = m0 + mf * 16 + (lane & 15);
                ldm4(ah[mf], abase + r * 80 + koff);
            }
            #pragma unroll
            for (int nb = 0; nb < 4; nb++) {
                const uint32_t r = n0w + nb * 16 + (lane & 7) + ((lane >> 4) << 3);
                const uint32_t kh = (lane >> 3) & 1;
                ldm4(bb[nb], bbase + r * 80 + ks * 32 + kh * 16);
            }
            #pragma unroll
            for (int mf = 0; mf < 2; mf++)
                #pragma unroll
                for (int nf = 0; nf < 8; nf++)
                    mma16816(acc[mf][nf], ah[mf], &bb[nf >> 1][(nf & 1) * 2]);
        }
    }
    __syncthreads();

    // ---- epilogue: accums -> smem [m][n] ----
    float* es = reinterpret_cast<float*>(smh);
    #pragma unroll
    for (int mf = 0; mf < 2; mf++)
        #pragma unroll
        for (int nf = 0; nf < 8; nf++) {
            const int row = m0 + mf * 16 + (lane >> 2);
            const int col = n0w + nf * 8 + 2 * (lane & 3);
            es[row * EPI_PIT + col]           = acc[mf][nf][0];
            es[row * EPI_PIT + col + 1]       = acc[mf][nf][1];
            es[(row + 8) * EPI_PIT + col]     = acc[mf][nf][2];
            es[(row + 8) * EPI_PIT + col + 1] = acc[mf][nf][3];
        }
    __syncthreads();

    // ---- per-row inhibition + LayerNorm; warp w -> rows 4w..4w+3 ----
    float sc[8], gm[8], bt[8], av[ITq];
    #pragma unroll
    for (int j = 0; j < 8; j++) {
        sc[j] = scales[tok * Hq + 32 * j + lane];
        gm[j] = gamma [tok * Hq + 32 * j + lane];
        bt[j] = beta  [tok * Hq + 32 * j + lane];
    }
    #pragma unroll
    for (int i = 0; i < ITq; i++) av[i] = alphas[tok * ITq + i];

    constexpr float INVH = 1.0f / (float)Hq;
    #pragma unroll
    for (int rr = 0; rr < 4; rr++) {
        const int lrow = wid * 4 + rr;
        float xt[8], xv[8];
        #pragma unroll
        for (int j = 0; j < 8; j++) {
            xt[j] = fmaxf(es[lrow * EPI_PIT + 32 * j + lane], 0.0f);
            xv[j] = es[lrow * EPI_PIT + 256 + 32 * j + lane];
        }
        #pragma unroll
        for (int it = 0; it < ITq; it++) {
            float s = 0.0f;
            #pragma unroll
            for (int j = 0; j < 8; j++) s += xt[j];
            #pragma unroll
            for (int off = 16; off > 0; off >>= 1)
                s += __shfl_xor_sync(0xffffffffu, s, off);
            const float d = av[it] * s * INVH;
            #pragma unroll
            for (int j = 0; j < 8; j++) xt[j] = fmaxf(xt[j] - d, 0.0f);
        }
        float sv[8], sum = 0.0f, sq = 0.0f;
        #pragma unroll
        for (int j = 0; j < 8; j++) {
            sv[j] = sc[j] * xt[j] * xv[j];
            sum += sv[j];
            sq  += sv[j] * sv[j];
        }
        #pragma unroll
        for (int off = 16; off > 0; off >>= 1) {
            sum += __shfl_xor_sync(0xffffffffu, sum, off);
            sq  += __shfl_xor_sync(0xffffffffu, sq,  off);
        }
        const float mu  = sum * INVH;
        const float var = fmaxf(sq * INVH - mu * mu, 0.0f);
        const float inv = rsqrtf(var + EPSq);
        const int b = b0 + lrow;
        float* op = out + ((size_t)b * Tq + tok) * Hq;
        #pragma unroll
        for (int j = 0; j < 8; j++)
            op[32 * j + lane] = (sv[j] - mu) * inv * gm[j] + bt[j];
    }
}

// ---------------- host launch ----------------
extern "C" void kernel_launch(void* const* d_in, const int* in_sizes, int n_in,
                              void* d_out, int out_size) {
    const float* x      = (const float*)d_in[0];
    const float* w_in   = (const float*)d_in[1];
    const float* w_val  = (const float*)d_in[2];
    const float* alphas = (const float*)d_in[3];
    const float* scales = (const float*)d_in[4];
    const float* gamma  = (const float*)d_in[5];
    const float* beta   = (const float*)d_in[6];
    float* out = (float*)d_out;

    convert_kernel<<<1024 + 8192, 256>>>(x, w_in, w_val);

    cudaFuncSetAttribute(gemm_fused_kernel,
                         cudaFuncAttributeMaxDynamicSharedMemorySize, SMEM_BYTES);
    dim3 grid(Bq / MT, Tq);
    gemm_fused_kernel<<<grid, 512, SMEM_BYTES>>>(alphas, scales, gamma, beta, out);
}

// round 5
// speedup vs baseline: 7.4870x; 1.4066x over previous
#include <cuda_runtime.h>
#include <cuda_fp16.h>
#include <cstdint>

// ---------------- problem constants ----------------
constexpr int Bq = 4096;
constexpr int Eq = 512;   // K
constexpr int Tq = 32;
constexpr int Hq = 256;
constexpr int ITq = 5;
constexpr int NN = 512;   // hidden(256) || value(256)
#define EPSq 1e-6f

// ---------------- GEMM tiling ----------------
constexpr int MT  = 64;            // CTA rows (batch)
constexpr int KC  = 64;            // k per chunk (64 halves = 128 B rows)
constexpr int NCH = Eq / KC;       // 8 chunks
constexpr int A_BYTES = MT * 128;  // 8192
constexpr int B_BYTES = NN * 128;  // 65536
constexpr int STAGE   = A_BYTES + B_BYTES;   // 73728
constexpr int NSTG    = 3;
constexpr int EPI_PIT = NN + 8;    // floats
constexpr int SMEM_BYTES = NSTG * STAGE;     // 221184 (>= epilogue 133120)

// ---------------- device scratch (chunked, pre-swizzled fp16) -------------
// xc: [mtile(64)][kc(8)][64 rows x 128 B]     = 4 MB
// wc: [tok(32)][kc(8)][512 rows x 128 B]      = 16 MB
__device__ __align__(256) __half g_xc[(size_t)64 * 8 * 4096];
__device__ __align__(256) __half g_wc[(size_t)32 * 8 * 32768];

// ---------------- asm helpers (sm_90 baseline, compute_103-safe) ----------
__device__ __forceinline__ uint32_t smem_u32(const void* p) {
    uint32_t a;
    asm("{ .reg .u64 t; cvta.to.shared.u64 t, %1; cvt.u32.u64 %0, t; }"
        : "=r"(a) : "l"(p));
    return a;
}
#define MBAR_INIT(addr, cnt) \
    asm volatile("mbarrier.init.shared.b64 [%0], %1;" :: "r"(addr), "r"(cnt) : "memory")
#define MBAR_EXPECT_TX(addr, bytes) \
    asm volatile("mbarrier.arrive.expect_tx.shared.b64 _, [%0], %1;" \
                 :: "r"(addr), "r"(bytes) : "memory")
#define MBAR_WAIT(addr, ph) do {                                              \
    asm volatile(                                                             \
        "{\n\t.reg .pred P;\n\t"                                              \
        "WL_%=:\n\t"                                                          \
        "mbarrier.try_wait.parity.shared.b64 P, [%0], %1;\n\t"                \
        "@P bra.uni WD_%=;\n\t"                                               \
        "bra.uni WL_%=;\n\t"                                                  \
        "WD_%=:\n\t}"                                                         \
        :: "r"(addr), "r"(ph) : "memory");                                    \
} while (0)
#define BULK_G2S(dst, src, bytes, mbar) \
    asm volatile("cp.async.bulk.shared::cluster.global.mbarrier::complete_tx::bytes " \
                 "[%0], [%1], %2, [%3];" \
                 :: "r"(dst), "l"(src), "r"(bytes), "r"(mbar) : "memory")

__device__ __forceinline__ void ldm4(uint32_t* r, uint32_t addr) {
    asm volatile("ldmatrix.sync.aligned.m8n8.x4.shared.b16 {%0,%1,%2,%3}, [%4];"
        : "=r"(r[0]), "=r"(r[1]), "=r"(r[2]), "=r"(r[3]) : "r"(addr));
}
__device__ __forceinline__ void mma16816(float* d, const uint32_t* a,
                                         const uint32_t* b) {
    asm volatile(
        "mma.sync.aligned.m16n8k16.row.col.f32.f16.f16.f32 "
        "{%0,%1,%2,%3},{%4,%5,%6,%7},{%8,%9},{%0,%1,%2,%3};"
        : "+f"(d[0]), "+f"(d[1]), "+f"(d[2]), "+f"(d[3])
        : "r"(a[0]), "r"(a[1]), "r"(a[2]), "r"(a[3]), "r"(b[0]), "r"(b[1]));
}

// swizzle within a 128-B row: XOR 16B-granule column by (row & 7)
__device__ __forceinline__ uint32_t swz(uint32_t row, uint32_t kbyte) {
    return row * 128u + (kbyte ^ ((row & 7u) << 4));
}

// ---------------- kernel 1: fused conversions into chunked scratch --------
// blocks [0,1024):     x fp32 -> swizzled chunked fp16
// blocks [1024,9216):  w transpose+convert -> swizzled chunked fp16
__global__ __launch_bounds__(256)
void convert_kernel(const float* __restrict__ x,
                    const float* __restrict__ w_in,
                    const float* __restrict__ w_val) {
    __shared__ float tile[32][33];
    if (blockIdx.x < 1024) {
        const int g  = blockIdx.x * 256 + threadIdx.x;   // 0..262143
        const int b  = g >> 6;            // batch row
        const int eg = g & 63;            // e-group (8 halves)
        const int e0 = eg * 8;
        __half h[8];
        const float* src = x + (size_t)b * Eq + e0;
        #pragma unroll
        for (int j = 0; j < 8; j++) h[j] = __float2half_rn(src[j]);
        const int kc = e0 >> 6;
        const uint32_t kb = (uint32_t)(e0 & 63) * 2;
        const uint32_t off = swz((uint32_t)(b & 63), kb);   // bytes in 8KB tile
        __half* dst = g_xc + (((size_t)(b >> 6) * 8 + kc) << 12) + (off >> 1);
        *reinterpret_cast<uint4*>(dst) = *reinterpret_cast<uint4*>(h);
        return;
    }
    const int bz = blockIdx.x - 1024;       // 0..8191
    const int e0 = (bz & 15) * 32;
    const int h0 = ((bz >> 4) & 7) * 32;
    const int z  = bz >> 7;                 // 0..63
    const int m  = z >> 5;                  // 0: w_in, 1: w_val
    const int t  = z & 31;
    const float* src = (m ? w_val : w_in) + (size_t)t * Eq * Hq;
    const int tx = threadIdx.x & 31;
    const int ty = threadIdx.x >> 5;
    #pragma unroll
    for (int r = ty; r < 32; r += 8)
        tile[r][tx] = src[(size_t)(e0 + r) * Hq + h0 + tx];
    __syncthreads();
    // write: thread = (hr, j); hr = local h row, j = 8-byte group (4 halves)
    const int hr = threadIdx.x >> 3;        // 0..31
    const int j  = threadIdx.x & 7;         // 0..7
    const int n  = m * 256 + h0 + hr;       // output row 0..511
    const int kc = e0 >> 6;
    const uint32_t kbyte = (uint32_t)(e0 & 63) * 2 + j * 8;
    __half hv[4];
    #pragma unroll
    for (int q = 0; q < 4; q++)
        hv[q] = __float2half_rn(tile[j * 4 + q][hr]);
    const uint32_t off = swz((uint32_t)n, kbyte);   // bit3 (j*8) unaffected by XOR
    __half* dst = g_wc + (((size_t)t * 8 + kc) << 15) + (off >> 1);
    *reinterpret_cast<uint2*>(dst) = *reinterpret_cast<uint2*>(hv);
}

// ---------------- kernel 2: fused GEMM (bulk-copy pipeline) + epilogue ----
__global__ __launch_bounds__(512, 1)
void gemm_fused_kernel(const float* __restrict__ alphas,
                       const float* __restrict__ scales,
                       const float* __restrict__ gamma,
                       const float* __restrict__ beta,
                       float* __restrict__ out)
{
    extern __shared__ __align__(128) char smem[];
    __shared__ uint64_t mbar_store[NSTG];
    const uint32_t sb = smem_u32(smem);
    const uint32_t mb = smem_u32(mbar_store);

    const int tid  = threadIdx.x;
    const int wid  = tid >> 5;
    const int lane = tid & 31;
    const int m0   = (wid >> 3) * 32;   // warp m origin (0/32)
    const int n0w  = (wid & 7) * 64;    // warp n origin (0..448)

    const int mtile = blockIdx.x;       // 0..63
    const int tok   = blockIdx.y;       // 0..31
    const int b0    = mtile * MT;

    if (tid == 0) {
        #pragma unroll
        for (int s = 0; s < NSTG; s++) MBAR_INIT(mb + s * 8, 1);
    }
    __syncthreads();

    auto issue = [&](int c) {
        const int s = c % NSTG;
        const uint32_t base = sb + (uint32_t)s * STAGE;
        MBAR_EXPECT_TX(mb + s * 8, (uint32_t)STAGE);
        const __half* asrc = g_xc + (((size_t)mtile * 8 + c) << 12);
        const __half* bsrc = g_wc + (((size_t)tok   * 8 + c) << 15);
        BULK_G2S(base,           asrc, (uint32_t)A_BYTES, mb + s * 8);
        BULK_G2S(base + A_BYTES, bsrc, (uint32_t)B_BYTES, mb + s * 8);
    };

    if (tid == 0) { issue(0); issue(1); issue(2); }

    float acc[2][8][4];
    #pragma unroll
    for (int i = 0; i < 2; i++)
        #pragma unroll
        for (int j = 0; j < 8; j++)
            #pragma unroll
            for (int k = 0; k < 4; k++) acc[i][j][k] = 0.0f;

    for (int c = 0; c < NCH; c++) {
        const int s = c % NSTG;
        MBAR_WAIT(mb + s * 8, (c / NSTG) & 1);
        const uint32_t abase = sb + (uint32_t)s * STAGE;
        const uint32_t bbase = abase + A_BYTES;

        #pragma unroll
        for (int ks = 0; ks < 4; ks++) {
            uint32_t ah[2][4], bb[4][4];
            #pragma unroll
            for (int mf = 0; mf < 2; mf++) {
                const uint32_t r  = m0 + mf * 16 + (lane & 15);
                const uint32_t kb = ks * 32 + ((lane >> 4) << 4);
                ldm4(ah[mf], abase + swz(r, kb));
            }
            #pragma unroll
            for (int nb = 0; nb < 4; nb++) {
                const uint32_t r  = n0w + nb * 16 + (lane & 7) + ((lane >> 4) << 3);
                const uint32_t kb = ks * 32 + (((lane >> 3) & 1) << 4);
                ldm4(bb[nb], bbase + swz(r, kb));
            }
            #pragma unroll
            for (int mf = 0; mf < 2; mf++)
                #pragma unroll
                for (int nf = 0; nf < 8; nf++)
                    mma16816(acc[mf][nf], ah[mf], &bb[nf >> 1][(nf & 1) * 2]);
        }
        __syncthreads();
        if (tid == 0 && c + NSTG < NCH) issue(c + NSTG);
    }

    // ---- epilogue: accums -> smem [m][n] (aliases stage memory) ----
    float* es = reinterpret_cast<float*>(smem);
    #pragma unroll
    for (int mf = 0; mf < 2; mf++)
        #pragma unroll
        for (int nf = 0; nf < 8; nf++) {
            const int row = m0 + mf * 16 + (lane >> 2);
            const int col = n0w + nf * 8 + 2 * (lane & 3);
            es[row * EPI_PIT + col]           = acc[mf][nf][0];
            es[row * EPI_PIT + col + 1]       = acc[mf][nf][1];
            es[(row + 8) * EPI_PIT + col]     = acc[mf][nf][2];
            es[(row + 8) * EPI_PIT + col + 1] = acc[mf][nf][3];
        }
    __syncthreads();

    // ---- per-row inhibition + LayerNorm; warp w -> rows 4w..4w+3 ----
    float sc[8], gm[8], bt[8], av[ITq];
    #pragma unroll
    for (int j = 0; j < 8; j++) {
        sc[j] = scales[tok * Hq + 32 * j + lane];
        gm[j] = gamma [tok * Hq + 32 * j + lane];
        bt[j] = beta  [tok * Hq + 32 * j + lane];
    }
    #pragma unroll
    for (int i = 0; i < ITq; i++) av[i] = alphas[tok * ITq + i];

    constexpr float INVH = 1.0f / (float)Hq;
    #pragma unroll
    for (int rr = 0; rr < 4; rr++) {
        const int lrow = wid * 4 + rr;
        float xt[8], xv[8];
        #pragma unroll
        for (int j = 0; j < 8; j++) {
            xt[j] = fmaxf(es[lrow * EPI_PIT + 32 * j + lane], 0.0f);
            xv[j] = es[lrow * EPI_PIT + 256 + 32 * j + lane];
        }
        #pragma unroll
        for (int it = 0; it < ITq; it++) {
            float s = 0.0f;
            #pragma unroll
            for (int j = 0; j < 8; j++) s += xt[j];
            #pragma unroll
            for (int off = 16; off > 0; off >>= 1)
                s += __shfl_xor_sync(0xffffffffu, s, off);
            const float d = av[it] * s * INVH;
            #pragma unroll
            for (int j = 0; j < 8; j++) xt[j] = fmaxf(xt[j] - d, 0.0f);
        }
        float sv[8], sum = 0.0f, sq = 0.0f;
        #pragma unroll
        for (int j = 0; j < 8; j++) {
            sv[j] = sc[j] * xt[j] * xv[j];
            sum += sv[j];
            sq  += sv[j] * sv[j];
        }
        #pragma unroll
        for (int off = 16; off > 0; off >>= 1) {
            sum += __shfl_xor_sync(0xffffffffu, sum, off);
            sq  += __shfl_xor_sync(0xffffffffu, sq,  off);
        }
        const float mu  = sum * INVH;
        const float var = fmaxf(sq * INVH - mu * mu, 0.0f);
        const float inv = rsqrtf(var + EPSq);
        const int b = b0 + lrow;
        float* op = out + ((size_t)b * Tq + tok) * Hq;
        #pragma unroll
        for (int j = 0; j < 8; j++)
            op[32 * j + lane] = (sv[j] - mu) * inv * gm[j] + bt[j];
    }
}

// ---------------- host launch ----------------
extern "C" void kernel_launch(void* const* d_in, const int* in_sizes, int n_in,
                              void* d_out, int out_size) {
    const float* x      = (const float*)d_in[0];
    const float* w_in   = (const float*)d_in[1];
    const float* w_val  = (const float*)d_in[2];
    const float* alphas = (const float*)d_in[3];
    const float* scales = (const float*)d_in[4];
    const float* gamma  = (const float*)d_in[5];
    const float* beta   = (const float*)d_in[6];
    float* out = (float*)d_out;

    convert_kernel<<<1024 + 8192, 256>>>(x, w_in, w_val);

    cudaFuncSetAttribute(gemm_fused_kernel,
                         cudaFuncAttributeMaxDynamicSharedMemorySize, SMEM_BYTES);
    dim3 grid(Bq / MT, Tq);
    gemm_fused_kernel<<<grid, 512, SMEM_BYTES>>>(alphas, scales, gamma, beta, out);
}

// round 6
// speedup vs baseline: 8.2976x; 1.1083x over previous
#include <cuda_runtime.h>
#include <cuda_fp16.h>
#include <cstdint>

// ---------------- problem constants ----------------
constexpr int Bq = 4096;
constexpr int Eq = 512;   // K
constexpr int Tq = 32;
constexpr int Hq = 256;
constexpr int ITq = 5;
constexpr int NN = 512;   // hidden(256) || value(256)
#define EPSq 1e-6f

// ---------------- GEMM tiling ----------------
constexpr int MT  = 32;            // CTA rows (batch)
constexpr int KC  = 32;            // k per chunk (32 halves = 64 B rows)
constexpr int NCH = Eq / KC;       // 16 chunks
constexpr int A_BYTES = MT * 64;   // 2048
constexpr int B_BYTES = NN * 64;   // 32768
constexpr int STAGE   = A_BYTES + B_BYTES;   // 34816
constexpr int NSTG    = 3;
constexpr int EPI_PIT = NN + 8;    // floats
constexpr int SMEM_BYTES = NSTG * STAGE;     // 104448 (>= epilogue 66560)

// ---------------- device scratch (chunked, pre-swizzled fp16) -------------
// xc: [mtile(128)][kc(16)][32 rows x 64 B]   = 4 MB
// wc: [tok(32)][kc(16)][512 rows x 64 B]     = 16 MB
__device__ __align__(256) __half g_xc[(size_t)128 * 16 * 1024];
__device__ __align__(256) __half g_wc[(size_t)32 * 16 * 16384];

// ---------------- asm helpers (sm_90 baseline, compute_103-safe) ----------
__device__ __forceinline__ uint32_t smem_u32(const void* p) {
    uint32_t a;
    asm("{ .reg .u64 t; cvta.to.shared.u64 t, %1; cvt.u32.u64 %0, t; }"
        : "=r"(a) : "l"(p));
    return a;
}
#define MBAR_INIT(addr, cnt) \
    asm volatile("mbarrier.init.shared.b64 [%0], %1;" :: "r"(addr), "r"(cnt) : "memory")
#define MBAR_EXPECT_TX(addr, bytes) \
    asm volatile("mbarrier.arrive.expect_tx.shared.b64 _, [%0], %1;" \
                 :: "r"(addr), "r"(bytes) : "memory")
#define MBAR_WAIT(addr, ph) do {                                              \
    asm volatile(                                                             \
        "{\n\t.reg .pred P;\n\t"                                              \
        "WL_%=:\n\t"                                                          \
        "mbarrier.try_wait.parity.shared.b64 P, [%0], %1;\n\t"                \
        "@P bra.uni WD_%=;\n\t"                                               \
        "bra.uni WL_%=;\n\t"                                                  \
        "WD_%=:\n\t}"                                                         \
        :: "r"(addr), "r"(ph) : "memory");                                    \
} while (0)
#define BULK_G2S(dst, src, bytes, mbar) \
    asm volatile("cp.async.bulk.shared::cluster.global.mbarrier::complete_tx::bytes " \
                 "[%0], [%1], %2, [%3];" \
                 :: "r"(dst), "l"(src), "r"(bytes), "r"(mbar) : "memory")

__device__ __forceinline__ void ldm4(uint32_t* r, uint32_t addr) {
    asm volatile("ldmatrix.sync.aligned.m8n8.x4.shared.b16 {%0,%1,%2,%3}, [%4];"
        : "=r"(r[0]), "=r"(r[1]), "=r"(r[2]), "=r"(r[3]) : "r"(addr));
}
__device__ __forceinline__ void mma16816(float* d, const uint32_t* a,
                                         const uint32_t* b) {
    asm volatile(
        "mma.sync.aligned.m16n8k16.row.col.f32.f16.f16.f32 "
        "{%0,%1,%2,%3},{%4,%5,%6,%7},{%8,%9},{%0,%1,%2,%3};"
        : "+f"(d[0]), "+f"(d[1]), "+f"(d[2]), "+f"(d[3])
        : "r"(a[0]), "r"(a[1]), "r"(a[2]), "r"(a[3]), "r"(b[0]), "r"(b[1]));
}

// swizzle within a 64-B row: XOR 16B-granule column by ((row>>1) & 3)
__device__ __forceinline__ uint32_t swz(uint32_t row, uint32_t kbyte) {
    return row * 64u + (kbyte ^ (((row >> 1) & 3u) << 4));
}

// ---------------- kernel 1: fused conversions into chunked scratch --------
// blocks [0,1024):     x fp32 -> swizzled chunked fp16
// blocks [1024,9216):  w transpose+convert -> swizzled chunked fp16
__global__ __launch_bounds__(256)
void convert_kernel(const float* __restrict__ x,
                    const float* __restrict__ w_in,
                    const float* __restrict__ w_val) {
    __shared__ float tile[32][33];
    if (blockIdx.x < 1024) {
        const int g  = blockIdx.x * 256 + threadIdx.x;   // 0..262143
        const int b  = g >> 6;            // batch row
        const int e0 = (g & 63) * 8;      // e start (8 halves = 16 B)
        __half h[8];
        const float* src = x + (size_t)b * Eq + e0;
        #pragma unroll
        for (int j = 0; j < 8; j++) h[j] = __float2half_rn(src[j]);
        const int kc = e0 >> 5;
        const uint32_t kb  = (uint32_t)(e0 & 31) * 2;       // 0,16,32,48
        const uint32_t off = swz((uint32_t)(b & 31), kb);   // bytes in 2KB tile
        __half* dst = g_xc + (((size_t)(b >> 5) * 16 + kc) << 10) + (off >> 1);
        *reinterpret_cast<uint4*>(dst) = *reinterpret_cast<uint4*>(h);
        return;
    }
    const int bz = blockIdx.x - 1024;       // 0..8191
    const int e0 = (bz & 15) * 32;
    const int h0 = ((bz >> 4) & 7) * 32;
    const int z  = bz >> 7;                 // 0..63
    const int m  = z >> 5;                  // 0: w_in, 1: w_val
    const int t  = z & 31;
    const float* src = (m ? w_val : w_in) + (size_t)t * Eq * Hq;
    const int tx = threadIdx.x & 31;
    const int ty = threadIdx.x >> 5;
    #pragma unroll
    for (int r = ty; r < 32; r += 8)
        tile[r][tx] = src[(size_t)(e0 + r) * Hq + h0 + tx];
    __syncthreads();
    // write: thread = (hr, j); 4 halves (8 B) per thread
    const int hr = threadIdx.x >> 3;        // 0..31
    const int j  = threadIdx.x & 7;         // 0..7
    const int n  = m * 256 + h0 + hr;       // output row 0..511
    const int kc = e0 >> 5;                 // e0 multiple of 32
    __half hv[4];
    #pragma unroll
    for (int q = 0; q < 4; q++)
        hv[q] = __float2half_rn(tile[j * 4 + q][hr]);
    const uint32_t off = swz((uint32_t)n, (uint32_t)(j * 8) & ~7u) | ((j * 8) & 8);
    __half* dst = g_wc + (((size_t)t * 16 + kc) << 14) + (off >> 1);
    *reinterpret_cast<uint2*>(dst) = *reinterpret_cast<uint2*>(hv);
}

// ---------------- kernel 2: fused GEMM (bulk pipeline, 2 CTA/SM) ----------
__global__ __launch_bounds__(256, 2)
void gemm_fused_kernel(const float* __restrict__ alphas,
                       const float* __restrict__ scales,
                       const float* __restrict__ gamma,
                       const float* __restrict__ beta,
                       float* __restrict__ out)
{
    extern __shared__ __align__(128) char smem[];
    __shared__ uint64_t mbar_store[NSTG];
    const uint32_t sb = smem_u32(smem);
    const uint32_t mb = smem_u32(mbar_store);

    const int tid  = threadIdx.x;
    const int wid  = tid >> 5;        // 0..7
    const int lane = tid & 31;
    const int n0w  = wid * 64;        // warp n origin

    const int mtile = blockIdx.x;     // 0..127
    const int tok   = blockIdx.y;     // 0..31
    const int b0    = mtile * MT;

    if (tid == 0) {
        #pragma unroll
        for (int s = 0; s < NSTG; s++) MBAR_INIT(mb + s * 8, 1);
    }
    __syncthreads();

    auto issue = [&](int c) {
        const int s = c % NSTG;
        const uint32_t base = sb + (uint32_t)s * STAGE;
        MBAR_EXPECT_TX(mb + s * 8, (uint32_t)STAGE);
        const __half* asrc = g_xc + (((size_t)mtile * 16 + c) << 10);
        const __half* bsrc = g_wc + (((size_t)tok   * 16 + c) << 14);
        BULK_G2S(base,           asrc, (uint32_t)A_BYTES, mb + s * 8);
        BULK_G2S(base + A_BYTES, bsrc, (uint32_t)B_BYTES, mb + s * 8);
    };

    if (tid == 0) { issue(0); issue(1); issue(2); }

    float acc[2][8][4];
    #pragma unroll
    for (int i = 0; i < 2; i++)
        #pragma unroll
        for (int j = 0; j < 8; j++)
            #pragma unroll
            for (int k = 0; k < 4; k++) acc[i][j][k] = 0.0f;

    for (int c = 0; c < NCH; c++) {
        const int s = c % NSTG;
        MBAR_WAIT(mb + s * 8, (c / NSTG) & 1);
        const uint32_t abase = sb + (uint32_t)s * STAGE;
        const uint32_t bbase = abase + A_BYTES;

        #pragma unroll
        for (int ks = 0; ks < 2; ks++) {
            uint32_t ah[2][4], bb[4][4];
            #pragma unroll
            for (int mf = 0; mf < 2; mf++) {
                const uint32_t r  = mf * 16 + (lane & 15);
                const uint32_t kb = ks * 32 + ((lane >> 4) << 4);
                ldm4(ah[mf], abase + swz(r, kb));
            }
            #pragma unroll
            for (int nb = 0; nb < 4; nb++) {
                const uint32_t r  = n0w + nb * 16 + (lane & 7) + ((lane >> 4) << 3);
                const uint32_t kb = ks * 32 + (((lane >> 3) & 1) << 4);
                ldm4(bb[nb], bbase + swz(r, kb));
            }
            #pragma unroll
            for (int mf = 0; mf < 2; mf++)
                #pragma unroll
                for (int nf = 0; nf < 8; nf++)
                    mma16816(acc[mf][nf], ah[mf], &bb[nf >> 1][(nf & 1) * 2]);
        }
        __syncthreads();
        if (tid == 0 && c + NSTG < NCH) issue(c + NSTG);
    }

    // ---- epilogue: accums -> smem [m][n] (aliases stage memory) ----
    float* es = reinterpret_cast<float*>(smem);
    #pragma unroll
    for (int mf = 0; mf < 2; mf++)
        #pragma unroll
        for (int nf = 0; nf < 8; nf++) {
            const int row = mf * 16 + (lane >> 2);
            const int col = n0w + nf * 8 + 2 * (lane & 3);
            es[row * EPI_PIT + col]           = acc[mf][nf][0];
            es[row * EPI_PIT + col + 1]       = acc[mf][nf][1];
            es[(row + 8) * EPI_PIT + col]     = acc[mf][nf][2];
            es[(row + 8) * EPI_PIT + col + 1] = acc[mf][nf][3];
        }
    __syncthreads();

    // ---- per-row inhibition + LayerNorm; warp w -> rows 4w..4w+3 ----
    float sc[8], gm[8], bt[8], av[ITq];
    #pragma unroll
    for (int j = 0; j < 8; j++) {
        sc[j] = scales[tok * Hq + 32 * j + lane];
        gm[j] = gamma [tok * Hq + 32 * j + lane];
        bt[j] = beta  [tok * Hq + 32 * j + lane];
    }
    #pragma unroll
    for (int i = 0; i < ITq; i++) av[i] = alphas[tok * ITq + i];

    constexpr float INVH = 1.0f / (float)Hq;
    #pragma unroll
    for (int rr = 0; rr < 4; rr++) {
        const int lrow = wid * 4 + rr;
        float xt[8], xv[8];
        #pragma unroll
        for (int j = 0; j < 8; j++) {
            xt[j] = fmaxf(es[lrow * EPI_PIT + 32 * j + lane], 0.0f);
            xv[j] = es[lrow * EPI_PIT + 256 + 32 * j + lane];
        }
        #pragma unroll
        for (int it = 0; it < ITq; it++) {
            float s = 0.0f;
            #pragma unroll
            for (int j = 0; j < 8; j++) s += xt[j];
            #pragma unroll
            for (int off = 16; off > 0; off >>= 1)
                s += __shfl_xor_sync(0xffffffffu, s, off);
            const float d = av[it] * s * INVH;
            #pragma unroll
            for (int j = 0; j < 8; j++) xt[j] = fmaxf(xt[j] - d, 0.0f);
        }
        float sv[8], sum = 0.0f, sq = 0.0f;
        #pragma unroll
        for (int j = 0; j < 8; j++) {
            sv[j] = sc[j] * xt[j] * xv[j];
            sum += sv[j];
            sq  += sv[j] * sv[j];
        }
        #pragma unroll
        for (int off = 16; off > 0; off >>= 1) {
            sum += __shfl_xor_sync(0xffffffffu, sum, off);
            sq  += __shfl_xor_sync(0xffffffffu, sq,  off);
        }
        const float mu  = sum * INVH;
        const float var = fmaxf(sq * INVH - mu * mu, 0.0f);
        const float inv = rsqrtf(var + EPSq);
        const int b = b0 + lrow;
        float* op = out + ((size_t)b * Tq + tok) * Hq;
        #pragma unroll
        for (int j = 0; j < 8; j++)
            op[32 * j + lane] = (sv[j] - mu) * inv * gm[j] + bt[j];
    }
}

// ---------------- host launch ----------------
extern "C" void kernel_launch(void* const* d_in, const int* in_sizes, int n_in,
                              void* d_out, int out_size) {
    const float* x      = (const float*)d_in[0];
    const float* w_in   = (const float*)d_in[1];
    const float* w_val  = (const float*)d_in[2];
    const float* alphas = (const float*)d_in[3];
    const float* scales = (const float*)d_in[4];
    const float* gamma  = (const float*)d_in[5];
    const float* beta   = (const float*)d_in[6];
    float* out = (float*)d_out;

    convert_kernel<<<1024 + 8192, 256>>>(x, w_in, w_val);

    cudaFuncSetAttribute(gemm_fused_kernel,
                         cudaFuncAttributeMaxDynamicSharedMemorySize, SMEM_BYTES);
    dim3 grid(Bq / MT, Tq);
    gemm_fused_kernel<<<grid, 256, SMEM_BYTES>>>(alphas, scales, gamma, beta, out);
}

// round 7
// speedup vs baseline: 8.7086x; 1.0495x over previous
#include <cuda_runtime.h>
#include <cuda_fp16.h>
#include <cstdint>

// ---------------- problem constants ----------------
constexpr int Bq = 4096;
constexpr int Eq = 512;   // K
constexpr int Tq = 32;
constexpr int Hq = 256;
constexpr int ITq = 5;
#define EPSq 1e-6f

// ---------------- fragment-ready scratch ----------------
// A frags: [mtile 128][ks 32][mfrag 2][lane 32][8 halves]  = 4 MB
// B frags: [tok 32][ks 32][warp 8][f 8][lane 32][4 halves] = 16 MB
__device__ __align__(256) __half g_xa[(size_t)128 * 32 * 2 * 32 * 8];
__device__ __align__(256) __half g_xb[(size_t)32 * 32 * 8 * 8 * 32 * 4];

__device__ __forceinline__ void mma16816(float* d, const uint32_t* a,
                                         const uint32_t* b) {
    asm volatile(
        "mma.sync.aligned.m16n8k16.row.col.f32.f16.f16.f32 "
        "{%0,%1,%2,%3},{%4,%5,%6,%7},{%8,%9},{%0,%1,%2,%3};"
        : "+f"(d[0]), "+f"(d[1]), "+f"(d[2]), "+f"(d[3])
        : "r"(a[0]), "r"(a[1]), "r"(a[2]), "r"(a[3]), "r"(b[0]), "r"(b[1]));
}

// ---------------- kernel 1: x -> A fragments ----------------
// idx = [mtile][ks][mfrag][lane]; each thread emits one 16-byte a-frag slice.
// a0={ (r0,c0),(r0,c0+1) } a1={ (r0+8,c0),(r0+8,c0+1) }
// a2={ (r0,c0+8),(r0,c0+9) } a3={ (r0+8,c0+8),(r0+8,c0+9) }
__global__ __launch_bounds__(256)
void convert_a_kernel(const float* __restrict__ x) {
    const int idx   = blockIdx.x * 256 + threadIdx.x;
    const int lane  = idx & 31;
    const int mfrag = (idx >> 5) & 1;
    const int ks    = (idx >> 6) & 31;
    const int mtile = idx >> 11;
    const int r0 = mtile * 32 + mfrag * 16 + (lane >> 2);
    const int c0 = ks * 16 + 2 * (lane & 3);
    const float* xr0 = x + (size_t)r0 * Eq;
    const float* xr1 = xr0 + 8 * Eq;
    __half h[8];
    h[0] = __float2half_rn(xr0[c0]);     h[1] = __float2half_rn(xr0[c0 + 1]);
    h[2] = __float2half_rn(xr1[c0]);     h[3] = __float2half_rn(xr1[c0 + 1]);
    h[4] = __float2half_rn(xr0[c0 + 8]); h[5] = __float2half_rn(xr0[c0 + 9]);
    h[6] = __float2half_rn(xr1[c0 + 8]); h[7] = __float2half_rn(xr1[c0 + 9]);
    reinterpret_cast<uint4*>(g_xa)[idx] = *reinterpret_cast<uint4*>(h);
}

// ---------------- kernel 2: w -> B fragments ----------------
// b0={ B[k0][n],B[k0+1][n] }  b1={ B[k0+8][n],B[k0+9][n] }  (k=e, n=h)
// Warp strip mapping: warp wp owns hidden cols [wp*32,wp*32+32) (f=0..3)
// and value cols [256+wp*32, ...) (f=4..7) -> gating is lane-local later.
__global__ __launch_bounds__(256)
void convert_b_kernel(const float* __restrict__ w_in,
                      const float* __restrict__ w_val) {
    __shared__ float tile[32][33];
    const int bz = blockIdx.x;
    const int e0 = (bz & 15) * 32;
    const int h0 = ((bz >> 4) & 7) * 32;
    const int z  = bz >> 7;
    const int m  = z >> 5;
    const int t  = z & 31;
    const float* src = (m ? w_val : w_in) + (size_t)t * Eq * Hq;
    const int tx = threadIdx.x & 31;
    const int ty = threadIdx.x >> 5;
    #pragma unroll
    for (int r = ty; r < 32; r += 8)
        tile[r][tx] = src[(size_t)(e0 + r) * Hq + h0 + tx];
    __syncthreads();
    const int lane = threadIdx.x & 31;
    const int f    = (threadIdx.x >> 5) & 3;
    const int ksl  = threadIdx.x >> 7;            // 0/1
    const int ks   = (e0 >> 4) + ksl;
    const int k0   = ksl * 16 + 2 * (lane & 3);
    const int hc   = f * 8 + (lane >> 2);
    const int wp   = h0 >> 5;
    const int fi   = f + m * 4;
    __half hv[4];
    hv[0] = __float2half_rn(tile[k0][hc]);
    hv[1] = __float2half_rn(tile[k0 + 1][hc]);
    hv[2] = __float2half_rn(tile[k0 + 8][hc]);
    hv[3] = __float2half_rn(tile[k0 + 9][hc]);
    const size_t di = ((((size_t)t * 32 + ks) * 8 + wp) * 8 + fi) * 32 + lane;
    reinterpret_cast<uint2*>(g_xb)[di] = *reinterpret_cast<uint2*>(hv);
}

// ---------------- kernel 3: all-LDG register GEMM + fused epilogue ----------
__global__ __launch_bounds__(256, 2)
void gemm_fused_kernel(const float* __restrict__ alphas,
                       const float* __restrict__ scales,
                       const float* __restrict__ gamma,
                       const float* __restrict__ beta,
                       float* __restrict__ out)
{
    __shared__ float red[2][8][32];

    const int tid  = threadIdx.x;
    const int wid  = tid >> 5;
    const int lane = tid & 31;
    const int mtile = blockIdx.x;   // 0..127
    const int tok   = blockIdx.y;   // 0..31
    const int b0    = mtile * 32;

    const uint4* pa = reinterpret_cast<const uint4*>(g_xa)
                    + ((size_t)mtile * 32) * 2 * 32 + lane;
    const uint2* pb = reinterpret_cast<const uint2*>(g_xb)
                    + (((size_t)tok * 32) * 8 + wid) * 8 * 32 + lane;

    float acc[2][8][4];
    #pragma unroll
    for (int i = 0; i < 2; i++)
        #pragma unroll
        for (int j = 0; j < 8; j++)
            #pragma unroll
            for (int k = 0; k < 4; k++) acc[i][j][k] = 0.0f;

    uint4 a0[2], a1[2];
    uint2 bb0[8], bb1[8];

    #define LOAD_A(ks, A) do {                                   \
        A[0] = pa[(size_t)(ks) * 64];                            \
        A[1] = pa[(size_t)(ks) * 64 + 32];                       \
    } while (0)
    #define LOAD_B(ks, BB) do {                                  \
        _Pragma("unroll")                                        \
        for (int f = 0; f < 8; f++)                              \
            BB[f] = pb[(size_t)(ks) * 2048 + f * 32];            \
    } while (0)
    #define DO_MMA(A, BB) do {                                   \
        _Pragma("unroll")                                        \
        for (int mf = 0; mf < 2; mf++)                           \
            _Pragma("unroll")                                    \
            for (int f = 0; f < 8; f++)                          \
                mma16816(acc[mf][f],                             \
                         reinterpret_cast<const uint32_t*>(&A[mf]), \
                         reinterpret_cast<const uint32_t*>(&BB[f])); \
    } while (0)

    LOAD_A(0, a0); LOAD_B(0, bb0);
    #pragma unroll
    for (int ks = 0; ks < 32; ks += 2) {
        if (ks + 1 < 32) { LOAD_A(ks + 1, a1); LOAD_B(ks + 1, bb1); }
        DO_MMA(a0, bb0);
        if (ks + 2 < 32) { LOAD_A(ks + 2, a0); LOAD_B(ks + 2, bb0); }
        if (ks + 1 < 32) DO_MMA(a1, bb1);
    }

    // ---------------- epilogue (register-resident gating) ----------------
    // lane cols (hidden): col = wid*32 + f*8 + 2*(lane&3) + {0,1}; value = col+256
    // lane rows: mf*16 + (lane>>2) and +8
    float xt[2][4][4], vv[2][4][4];
    #pragma unroll
    for (int mf = 0; mf < 2; mf++)
        #pragma unroll
        for (int f = 0; f < 4; f++)
            #pragma unroll
            for (int c = 0; c < 4; c++) {
                xt[mf][f][c] = fmaxf(acc[mf][f][c], 0.0f);
                vv[mf][f][c] = acc[mf][f + 4][c];
            }

    float av[ITq];
    #pragma unroll
    for (int i = 0; i < ITq; i++) av[i] = alphas[tok * ITq + i];

    float2 sc[4], gm[4], bt[4];
    #pragma unroll
    for (int f = 0; f < 4; f++) {
        const int col = wid * 32 + f * 8 + 2 * (lane & 3);
        sc[f] = *reinterpret_cast<const float2*>(scales + tok * Hq + col);
        gm[f] = *reinterpret_cast<const float2*>(gamma  + tok * Hq + col);
        bt[f] = *reinterpret_cast<const float2*>(beta   + tok * Hq + col);
    }

    constexpr float INVH = 1.0f / (float)Hq;
    const int q = lane >> 2;            // row sub-index 0..7

    // ---- iterative inhibition: 5 x (partial reduce -> smem -> mean) ----
    #pragma unroll
    for (int it = 0; it < ITq; it++) {
        float plo[2], phi[2];
        #pragma unroll
        for (int mf = 0; mf < 2; mf++) {
            plo[mf] = 0.0f; phi[mf] = 0.0f;
            #pragma unroll
            for (int f = 0; f < 4; f++) {
                plo[mf] += xt[mf][f][0] + xt[mf][f][1];
                phi[mf] += xt[mf][f][2] + xt[mf][f][3];
            }
        }
        #pragma unroll
        for (int off = 1; off <= 2; off <<= 1) {
            #pragma unroll
            for (int mf = 0; mf < 2; mf++) {
                plo[mf] += __shfl_xor_sync(0xffffffffu, plo[mf], off);
                phi[mf] += __shfl_xor_sync(0xffffffffu, phi[mf], off);
            }
        }
        const int buf = it & 1;
        if ((lane & 3) == 0) {
            red[buf][wid][q]      = plo[0];
            red[buf][wid][q + 8]  = phi[0];
            red[buf][wid][q + 16] = plo[1];
            red[buf][wid][q + 24] = phi[1];
        }
        __syncthreads();
        float mlo[2], mhi[2];
        #pragma unroll
        for (int mf = 0; mf < 2; mf++) {
            const int rlo = mf * 16 + q;
            float slo = 0.0f, shi = 0.0f;
            #pragma unroll
            for (int w = 0; w < 8; w++) {
                slo += red[buf][w][rlo];
                shi += red[buf][w][rlo + 8];
            }
            mlo[mf] = slo * INVH; mhi[mf] = shi * INVH;
        }
        #pragma unroll
        for (int mf = 0; mf < 2; mf++) {
            const float dlo = av[it] * mlo[mf];
            const float dhi = av[it] * mhi[mf];
            #pragma unroll
            for (int f = 0; f < 4; f++) {
                xt[mf][f][0] = fmaxf(xt[mf][f][0] - dlo, 0.0f);
                xt[mf][f][1] = fmaxf(xt[mf][f][1] - dlo, 0.0f);
                xt[mf][f][2] = fmaxf(xt[mf][f][2] - dhi, 0.0f);
                xt[mf][f][3] = fmaxf(xt[mf][f][3] - dhi, 0.0f);
            }
        }
    }
    __syncthreads();   // protect red reuse below

    // ---- gated value + LayerNorm ----
    float s[2][4][4];
    float sumlo[2] = {0, 0}, sumhi[2] = {0, 0};
    float sqlo[2]  = {0, 0}, sqhi[2]  = {0, 0};
    #pragma unroll
    for (int mf = 0; mf < 2; mf++)
        #pragma unroll
        for (int f = 0; f < 4; f++) {
            s[mf][f][0] = sc[f].x * xt[mf][f][0] * vv[mf][f][0];
            s[mf][f][1] = sc[f].y * xt[mf][f][1] * vv[mf][f][1];
            s[mf][f][2] = sc[f].x * xt[mf][f][2] * vv[mf][f][2];
            s[mf][f][3] = sc[f].y * xt[mf][f][3] * vv[mf][f][3];
            sumlo[mf] += s[mf][f][0] + s[mf][f][1];
            sumhi[mf] += s[mf][f][2] + s[mf][f][3];
            sqlo[mf]  += s[mf][f][0] * s[mf][f][0] + s[mf][f][1] * s[mf][f][1];
            sqhi[mf]  += s[mf][f][2] * s[mf][f][2] + s[mf][f][3] * s[mf][f][3];
        }
    #pragma unroll
    for (int off = 1; off <= 2; off <<= 1) {
        #pragma unroll
        for (int mf = 0; mf < 2; mf++) {
            sumlo[mf] += __shfl_xor_sync(0xffffffffu, sumlo[mf], off);
            sumhi[mf] += __shfl_xor_sync(0xffffffffu, sumhi[mf], off);
            sqlo[mf]  += __shfl_xor_sync(0xffffffffu, sqlo[mf],  off);
            sqhi[mf]  += __shfl_xor_sync(0xffffffffu, sqhi[mf],  off);
        }
    }
    if ((lane & 3) == 0) {
        red[0][wid][q]      = sumlo[0];
        red[0][wid][q + 8]  = sumhi[0];
        red[0][wid][q + 16] = sumlo[1];
        red[0][wid][q + 24] = sumhi[1];
        red[1][wid][q]      = sqlo[0];
        red[1][wid][q + 8]  = sqhi[0];
        red[1][wid][q + 16] = sqlo[1];
        red[1][wid][q + 24] = sqhi[1];
    }
    __syncthreads();

    #pragma unroll
    for (int mf = 0; mf < 2; mf++) {
        const int rlo = mf * 16 + q;
        float slo = 0, shi = 0, qlo = 0, qhi = 0;
        #pragma unroll
        for (int w = 0; w < 8; w++) {
            slo += red[0][w][rlo];   shi += red[0][w][rlo + 8];
            qlo += red[1][w][rlo];   qhi += red[1][w][rlo + 8];
        }
        const float mulo = slo * INVH;
        const float muhi = shi * INVH;
        const float ilo  = rsqrtf(fmaxf(qlo * INVH - mulo * mulo, 0.0f) + EPSq);
        const float ihi  = rsqrtf(fmaxf(qhi * INVH - muhi * muhi, 0.0f) + EPSq);

        const int row_lo = b0 + mf * 16 + q;
        float* olo = out + ((size_t)row_lo * Tq + tok) * Hq;
        float* ohi = olo + (size_t)8 * Tq * Hq;
        #pragma unroll
        for (int f = 0; f < 4; f++) {
            const int col = wid * 32 + f * 8 + 2 * (lane & 3);
            float2 v0, v1;
            v0.x = (s[mf][f][0] - mulo) * ilo * gm[f].x + bt[f].x;
            v0.y = (s[mf][f][1] - mulo) * ilo * gm[f].y + bt[f].y;
            v1.x = (s[mf][f][2] - muhi) * ihi * gm[f].x + bt[f].x;
            v1.y = (s[mf][f][3] - muhi) * ihi * gm[f].y + bt[f].y;
            *reinterpret_cast<float2*>(olo + col) = v0;
            *reinterpret_cast<float2*>(ohi + col) = v1;
        }
    }
}

// ---------------- host launch ----------------
extern "C" void kernel_launch(void* const* d_in, const int* in_sizes, int n_in,
                              void* d_out, int out_size) {
    const float* x      = (const float*)d_in[0];
    const float* w_in   = (const float*)d_in[1];
    const float* w_val  = (const float*)d_in[2];
    const float* alphas = (const float*)d_in[3];
    const float* scales = (const float*)d_in[4];
    const float* gamma  = (const float*)d_in[5];
    const float* beta   = (const float*)d_in[6];
    float* out = (float*)d_out;

    convert_a_kernel<<<1024, 256>>>(x);
    convert_b_kernel<<<8192, 256>>>(w_in, w_val);

    dim3 grid(Bq / 32, Tq);
    gemm_fused_kernel<<<grid, 256>>>(alphas, scales, gamma, beta, out);
}